// round 10
// baseline (speedup 1.0000x reference)
#include <cuda_runtime.h>
#include <math.h>
#include <cstdint>
#include <float.h>

#define G3       24
#define NC       (G3 * G3 * G3)        // 13824 cells
#define THREADS  512
#define NWARPS   (THREADS / 32)
#define NB_MAX   160
#define MAXM     16384
#define MAXP     32768
#define MAXSTAGE 10240

// -------- device scratch (static; no allocations) --------
__device__ float4 g_pu[MAXP];            // preds: (px,py,pz,weight)
__device__ float4 g_ms[MAXM];            // cell-sorted model: (x,y,z,|g|^2)
__device__ int g_chist[NC];              // zeroed in Phase C each launch
__device__ int g_cstart[NC + 1];
__device__ int g_ccur[NC];
__device__ int g_bbmin[3] = {0x7fffffff, 0x7fffffff, 0x7fffffff};
__device__ int g_bbmax[3] = {(int)0x80000000, (int)0x80000000, (int)0x80000000};
__device__ float g_partials[NB_MAX];
__device__ unsigned int g_bar1, g_bar2, g_bar3, g_bar4, g_ticket;

__device__ __forceinline__ int f2ord(float f) {
    int i = __float_as_int(f);
    return i >= 0 ? i : (i ^ 0x7fffffff);
}
__device__ __forceinline__ float ord2f(int o) {
    return __int_as_float(o >= 0 ? o : (o ^ 0x7fffffff));
}

__device__ __forceinline__ void grid_bar(unsigned int* ctr, unsigned int tgt) {
    __syncthreads();
    if (threadIdx.x == 0) {
        __threadfence();
        atomicAdd(ctr, 1u);
        while (*((volatile unsigned int*)ctr) < tgt) { __nanosleep(64); }
        __threadfence();
    }
    __syncthreads();
}

// Exact ring search for one pred point. pts/s_start inlined so address space
// is provable (LDS for the staged path).
template <typename F4P>
__device__ __forceinline__ float ring_search(
    F4P pts, const int* s_start,
    float px, float py, float pz, float a,
    float ox, float oy, float oz,
    float hx, float hy, float hz,
    float ihx, float ihy, float ihz, float hmin)
{
    float qx = -2.0f * px, qy = -2.0f * py, qz = -2.0f * pz;
    int cx = (int)floorf((px - ox) * ihx);
    int cy = (int)floorf((py - oy) * ihy);
    int cz = (int)floorf((pz - oz) * ihz);
    cx = min(max(cx, 0), G3 - 1);
    cy = min(max(cy, 0), G3 - 1);
    cz = min(max(cz, 0), G3 - 1);

    float m = 3.0e37f;   // tracks min over (b - 2 p.g); dist^2 = a + m
    for (int k = 0; k < G3; k++) {
        if (k > 0) {
            float bd = (float)(k - 1) * hmin * 0.999f;
            if (bd * bd >= a + m) break;   // all remaining rings provably worse
        }
        int x0 = max(cx - k, 0), x1 = min(cx + k, G3 - 1);
        int y0 = max(cy - k, 0), y1 = min(cy + k, G3 - 1);
        int z0 = max(cz - k, 0), z1 = min(cz + k, G3 - 1);
        for (int x = x0; x <= x1; x++) {
            int adx = abs(x - cx);
            float lox = ox + (float)x * hx;
            float ddx = fmaxf(fmaxf(lox - px, px - (lox + hx)), 0.f);
            for (int y = y0; y <= y1; y++) {
                int axy = max(adx, abs(y - cy));
                float loy = oy + (float)y * hy;
                float ddy = fmaxf(fmaxf(loy - py, py - (loy + hy)), 0.f);
                float dd2 = fmaf(ddx, ddx, ddy * ddy);
                for (int z = z0; z <= z1; z++) {
                    if (max(axy, abs(z - cz)) != k) continue;   // ring shell only
                    float loz = oz + (float)z * hz;
                    float ddz = fmaxf(fmaxf(loz - pz, pz - (loz + hz)), 0.f);
                    float lb2 = fmaf(ddz, ddz, dd2);
                    if (lb2 * 0.999f >= a + m) continue;        // exact cell screen
                    int c = (x * G3 + y) * G3 + z;
                    int j0 = s_start[c], j1 = s_start[c + 1];
                    for (int j = j0; j < j1; j++) {
                        float4 g = pts[j];
                        float d = fmaf(qx, g.x, fmaf(qy, g.y, fmaf(qz, g.z, g.w)));
                        m = fminf(m, d);
                    }
                }
            }
        }
    }
    return m;
}

__global__ __launch_bounds__(THREADS, 1)
void cd_kernel(const float* __restrict__ vis,
               const float* __restrict__ tac,
               const float* __restrict__ model,
               const float* __restrict__ scale,
               const float* __restrict__ state,
               float* __restrict__ out,
               int nv, int nt, int nm,
               float wv, float wt) {
    extern __shared__ char smem_raw[];
    int* s_start = (int*)smem_raw;                                   // NC+1 ints
    float4* s_pts = (float4*)(smem_raw + (((NC + 1) * 4 + 15) & ~15));

    __shared__ float s_par[13];
    __shared__ float s_box[10];           // o[3], ih[3], h[3], hmin
    __shared__ int s_scan[THREADS];
    __shared__ float s_red[NWARPS];
    __shared__ float s_wbb[NWARPS][6];
    __shared__ int s_last;

    const int tid  = threadIdx.x;
    const int lane = tid & 31;
    const int warp = tid >> 5;
    const int ntot0 = nv + nt;
    const int ntot  = ntot0 < MAXP ? ntot0 : MAXP;
    const int nmm   = nm < MAXM ? nm : MAXM;
    const unsigned int GRID = gridDim.x;
    const int gstride = (int)GRID * THREADS;
    const int gtid = blockIdx.x * THREADS + tid;

    // ---- transform params ----
    if (tid == 0) {
        float oxs = state[3], oys = state[4], ozs = state[5];
        float sx = sinf(oxs), cxx = cosf(oxs);
        float sy = sinf(oys), cyy = cosf(oys);
        float sz = sinf(ozs), czz = cosf(ozs);
        s_par[0] = czz * cyy;
        s_par[1] = czz * sy * sx - sz * cxx;
        s_par[2] = czz * sy * cxx + sz * sx;
        s_par[3] = sz * cyy;
        s_par[4] = sz * sy * sx + czz * cxx;
        s_par[5] = sz * sy * cxx - czz * sx;
        s_par[6] = -sy;
        s_par[7] = cyy * sx;
        s_par[8] = cyy * cxx;
        s_par[9]  = state[0];
        s_par[10] = state[1];
        s_par[11] = state[2];
        s_par[12] = 1.0f / scale[0];
    }
    __syncthreads();

    // ============ Phase A: pred transform + joint bbox ============
    float bmn[3] = {FLT_MAX, FLT_MAX, FLT_MAX};
    float bmx[3] = {-FLT_MAX, -FLT_MAX, -FLT_MAX};
    for (int j = gtid; j < nmm; j += gstride) {
        float gx = model[3 * j], gy = model[3 * j + 1], gz = model[3 * j + 2];
        bmn[0] = fminf(bmn[0], gx); bmx[0] = fmaxf(bmx[0], gx);
        bmn[1] = fminf(bmn[1], gy); bmx[1] = fmaxf(bmx[1], gy);
        bmn[2] = fminf(bmn[2], gz); bmx[2] = fmaxf(bmx[2], gz);
    }
    for (int i = gtid; i < ntot; i += gstride) {
        const float* src; int idx; float w;
        if (i < nv) { src = vis; idx = i;      w = wv; }
        else        { src = tac; idx = i - nv; w = wt; }
        float vx = src[3 * idx + 0] - s_par[9];
        float vy = src[3 * idx + 1] - s_par[10];
        float vz = src[3 * idx + 2] - s_par[11];
        float inv_s = s_par[12];
        float px = (vx * s_par[0] + vy * s_par[3] + vz * s_par[6]) * inv_s;
        float py = (vx * s_par[1] + vy * s_par[4] + vz * s_par[7]) * inv_s;
        float pz = (vx * s_par[2] + vy * s_par[5] + vz * s_par[8]) * inv_s;
        g_pu[i] = make_float4(px, py, pz, w);
        bmn[0] = fminf(bmn[0], px); bmx[0] = fmaxf(bmx[0], px);
        bmn[1] = fminf(bmn[1], py); bmx[1] = fmaxf(bmx[1], py);
        bmn[2] = fminf(bmn[2], pz); bmx[2] = fmaxf(bmx[2], pz);
    }
    #pragma unroll
    for (int o = 16; o > 0; o >>= 1) {
        #pragma unroll
        for (int d = 0; d < 3; d++) {
            bmn[d] = fminf(bmn[d], __shfl_down_sync(0xffffffffu, bmn[d], o));
            bmx[d] = fmaxf(bmx[d], __shfl_down_sync(0xffffffffu, bmx[d], o));
        }
    }
    if (lane == 0) {
        #pragma unroll
        for (int d = 0; d < 3; d++) {
            s_wbb[warp][d] = bmn[d];
            s_wbb[warp][3 + d] = bmx[d];
        }
    }
    __syncthreads();
    if (tid < 3) {
        float v = s_wbb[0][tid];
        for (int w2 = 1; w2 < NWARPS; w2++) v = fminf(v, s_wbb[w2][tid]);
        atomicMin(&g_bbmin[tid], f2ord(v));
    } else if (tid < 6) {
        int d = tid - 3;
        float v = s_wbb[0][3 + d];
        for (int w2 = 1; w2 < NWARPS; w2++) v = fmaxf(v, s_wbb[w2][3 + d]);
        atomicMax(&g_bbmax[d], f2ord(v));
    }
    grid_bar(&g_bar1, GRID);

    // decode bbox -> grid geometry
    if (tid == 0) {
        float hmin = FLT_MAX;
        for (int d = 0; d < 3; d++) {
            float mn = ord2f(g_bbmin[d]), mx = ord2f(g_bbmax[d]);
            float span = mx - mn;
            float pad = span * 1e-3f + 1e-6f;
            float o = mn - pad, s2 = span + 2.0f * pad;
            s_box[d] = o;
            s_box[3 + d] = (float)G3 / s2;
            s_box[6 + d] = s2 / (float)G3;
            hmin = fminf(hmin, s2 / (float)G3);
        }
        s_box[9] = hmin;
    }
    __syncthreads();
    const float ox = s_box[0], oy = s_box[1], oz = s_box[2];
    const float ihx = s_box[3], ihy = s_box[4], ihz = s_box[5];
    const float hx = s_box[6], hy = s_box[7], hz = s_box[8];
    const float hmin = s_box[9];

    // ============ Phase B: cell histogram ============
    for (int j = gtid; j < nmm; j += gstride) {
        float gx = model[3 * j], gy = model[3 * j + 1], gz = model[3 * j + 2];
        int cx = min(max((int)floorf((gx - ox) * ihx), 0), G3 - 1);
        int cy = min(max((int)floorf((gy - oy) * ihy), 0), G3 - 1);
        int cz = min(max((int)floorf((gz - oz) * ihz), 0), G3 - 1);
        atomicAdd(&g_chist[(cx * G3 + cy) * G3 + cz], 1);
    }
    grid_bar(&g_bar2, GRID);

    // ============ Phase C: CTA0 prefix-sums + reset hist ============
    if (blockIdx.x == 0) {
        const int PER = NC / THREADS;   // 27 exactly
        int base = tid * PER;
        int loc[PER];
        int s = 0;
        #pragma unroll
        for (int r = 0; r < PER; r++) { loc[r] = g_chist[base + r]; s += loc[r]; }
        s_scan[tid] = s;
        __syncthreads();
        for (int off = 1; off < THREADS; off <<= 1) {
            int t = (tid >= off) ? s_scan[tid - off] : 0;
            __syncthreads();
            s_scan[tid] += t;
            __syncthreads();
        }
        int run = s_scan[tid] - s;
        #pragma unroll
        for (int r = 0; r < PER; r++) {
            g_cstart[base + r] = run;
            g_ccur[base + r] = run;
            run += loc[r];
            g_chist[base + r] = 0;          // reset for next replay
        }
        if (tid == THREADS - 1) g_cstart[NC] = run;
        __threadfence();
    }
    grid_bar(&g_bar3, GRID);

    // ============ Phase D: scatter model into cell order ============
    for (int j = gtid; j < nmm; j += gstride) {
        float gx = model[3 * j], gy = model[3 * j + 1], gz = model[3 * j + 2];
        int cx = min(max((int)floorf((gx - ox) * ihx), 0), G3 - 1);
        int cy = min(max((int)floorf((gy - oy) * ihy), 0), G3 - 1);
        int cz = min(max((int)floorf((gz - oz) * ihz), 0), G3 - 1);
        int pos = atomicAdd(&g_ccur[(cx * G3 + cy) * G3 + cz], 1);
        g_ms[pos] = make_float4(gx, gy, gz, fmaf(gx, gx, fmaf(gy, gy, gz * gz)));
    }
    grid_bar(&g_bar4, GRID);

    // ============ Phase E: stage + per-pred ring search ============
    const bool staged = (nmm <= MAXSTAGE);
    for (int c = tid; c <= NC; c += THREADS) s_start[c] = g_cstart[c];
    if (staged)
        for (int j = tid; j < nmm; j += THREADS) s_pts[j] = g_ms[j];
    __syncthreads();

    float sum = 0.0f;
    const int nwtot = (int)GRID * NWARPS;
    const int gw = blockIdx.x * NWARPS + warp;
    for (int i = gw + nwtot * lane; i < ntot; i += nwtot * 32) {
        float4 P = g_pu[i];
        float a = fmaf(P.x, P.x, fmaf(P.y, P.y, P.z * P.z));
        float m;
        if (staged)
            m = ring_search(s_pts, s_start, P.x, P.y, P.z, a,
                            ox, oy, oz, hx, hy, hz, ihx, ihy, ihz, hmin);
        else
            m = ring_search((const float4*)g_ms, s_start, P.x, P.y, P.z, a,
                            ox, oy, oz, hx, hy, hz, ihx, ihy, ihz, hmin);
        sum += (a + m) * P.w;
    }

    // block reduction (fixed tree)
    #pragma unroll
    for (int o = 16; o > 0; o >>= 1)
        sum += __shfl_down_sync(0xffffffffu, sum, o);
    if (lane == 0) s_red[warp] = sum;
    __syncthreads();
    if (tid == 0) {
        float v = 0.0f;
        for (int w2 = 0; w2 < NWARPS; w2++) v += s_red[w2];
        g_partials[blockIdx.x] = v;
    }
    __syncthreads();

    // ---- last-CTA fused final reduction + scratch resets ----
    if (tid == 0) {
        __threadfence();
        unsigned int t = atomicAdd(&g_ticket, 1u);
        s_last = (t == GRID - 1u) ? 1 : 0;
    }
    __syncthreads();
    if (s_last && warp == 0) {
        float s = 0.0f;
        for (int b = lane; b < (int)GRID; b += 32)
            s += *((volatile float*)&g_partials[b]);
        #pragma unroll
        for (int o = 16; o > 0; o >>= 1)
            s += __shfl_down_sync(0xffffffffu, s, o);
        if (lane == 0) {
            out[0] = s;
            // resets for next graph replay (all CTAs are past every use)
            g_ticket = 0; g_bar1 = 0; g_bar2 = 0; g_bar3 = 0; g_bar4 = 0;
            for (int d = 0; d < 3; d++) {
                g_bbmin[d] = 0x7fffffff;
                g_bbmax[d] = (int)0x80000000;
            }
        }
    }
}

extern "C" void kernel_launch(void* const* d_in, const int* in_sizes, int n_in,
                              void* d_out, int out_size) {
    const float* vis   = (const float*)d_in[0];  // visual_points  (16384,3)
    const float* tac   = (const float*)d_in[1];  // tactile_points (2048,3)
    const float* model = (const float*)d_in[2];  // model_points   (8192,3)
    const float* scale = (const float*)d_in[3];  // scalar
    const float* state = (const float*)d_in[4];  // (6,)
    float* out = (float*)d_out;

    int nv = in_sizes[0] / 3;
    int nt = in_sizes[1] / 3;
    int nm = in_sizes[2] / 3;

    int grid = 144;   // all-resident (1 CTA/SM at this smem size) for barriers

    int nm_staged = nm < MAXSTAGE ? nm : MAXSTAGE;
    size_t smem = (size_t)(((NC + 1) * 4 + 15) & ~15) + (size_t)nm_staged * 16;
    cudaFuncSetAttribute(cd_kernel, cudaFuncAttributeMaxDynamicSharedMemorySize,
                         (int)smem);

    float wv = 1.0f / (float)nv;
    float wt = 0.1f / (float)nt;

    cd_kernel<<<grid, THREADS, smem>>>(vis, tac, model, scale, state, out,
                                       nv, nt, nm, wv, wt);
}

// round 11
// speedup vs baseline: 12.4661x; 12.4661x over previous
#include <cuda_runtime.h>
#include <math.h>
#include <cstdint>
#include <float.h>

#define NBIN     512
#define BINSCALE 64.0f        // bin = r * 64, covers r in [0, 8)
#define THREADS  512
#define NWARP    16
#define NB_MAX   256
#define MAXM     16384
#define MAXP     32768
#define SLAB     1536

// -------- device scratch (static; no allocations) --------
__device__ float4 g_ms[MAXM];            // norm-sorted model (x,y,z,|g|^2)
__device__ float4 g_pu[MAXP];            // unsorted pred (px,py,pz,a)
__device__ float2 g_pu2[MAXP];           // unsorted pred (w,r)
__device__ float4 g_ps[MAXP];            // sorted pred (qx,qy,qz,a)
__device__ float2 g_ps2[MAXP];           // sorted pred (w,r)
__device__ int g_mhist[NBIN], g_phist[NBIN];   // zero; reset each launch
__device__ int g_mcur[NBIN], g_pcur[NBIN];     // zero; reset each launch
__device__ float g_partials[NB_MAX];
__device__ unsigned int g_bar1, g_bar2, g_ticket;

__device__ __forceinline__ int norm_bin(float r) {
    int b = (int)(r * BINSCALE);
    if (b < 0) b = 0;
    if (b > NBIN - 1) b = NBIN - 1;
    return b;
}

__device__ __forceinline__ void grid_bar(unsigned int* ctr, unsigned int tgt) {
    __syncthreads();
    if (threadIdx.x == 0) {
        __threadfence();
        atomicAdd(ctr, 1u);
        while (*((volatile unsigned int*)ctr) < tgt) { }
        __threadfence();
    }
    __syncthreads();
}

// Pack rows [row0, row0+n) of g_ms into pair-interleaved smem records.
__device__ __forceinline__ void pack_rows(float* s_model, int row0, int n, int tid) {
    for (int e = tid; e < n; e += THREADS) {
        float4 gm = g_ms[row0 + e];
        int p = e >> 1, o = e & 1;
        s_model[p * 8 + 0 + o] = gm.x;
        s_model[p * 8 + 2 + o] = gm.y;
        s_model[p * 8 + 4 + o] = gm.z;
        s_model[p * 8 + 6 + o] = gm.w;
    }
    if ((n & 1) && tid == 0) {
        int p = n >> 1;
        s_model[p * 8 + 1] = 0.f; s_model[p * 8 + 3] = 0.f;
        s_model[p * 8 + 5] = 0.f; s_model[p * 8 + 7] = 3.0e37f;
    }
}

// Warp-sliced packed f32x2 min-scan over npairs records.
__device__ __forceinline__ void scan_pairs(const float* s_model, int npairs, int warp,
                                           const uint64_t* qx2, const uint64_t* qy2,
                                           const uint64_t* qz2, float* m_lo, float* m_hi) {
    int ps = (npairs + NWARP - 1) / NWARP;
    int pb = warp * ps; if (pb > npairs) pb = npairs;
    int pe = pb + ps;   if (pe > npairs) pe = npairs;
    uint32_t addr;
    {
        uint64_t a64;
        asm("cvta.to.shared.u64 %0, %1;" : "=l"(a64) : "l"(s_model + (size_t)pb * 8));
        addr = (uint32_t)a64;
    }
    #pragma unroll 4
    for (int p = pb; p < pe; ++p, addr += 32u) {
        uint64_t x2, y2, z2, w2;
        asm("ld.shared.v2.u64 {%0,%1}, [%2];"    : "=l"(x2), "=l"(y2) : "r"(addr));
        asm("ld.shared.v2.u64 {%0,%1}, [%2+16];" : "=l"(z2), "=l"(w2) : "r"(addr));
        #pragma unroll
        for (int k = 0; k < 4; k++) {
            uint64_t d2;
            asm("fma.rn.f32x2 %0, %1, %2, %3;" : "=l"(d2) : "l"(qz2[k]), "l"(z2), "l"(w2));
            asm("fma.rn.f32x2 %0, %1, %2, %0;" : "+l"(d2) : "l"(qy2[k]), "l"(y2));
            asm("fma.rn.f32x2 %0, %1, %2, %0;" : "+l"(d2) : "l"(qx2[k]), "l"(x2));
            float dlo, dhi;
            asm("mov.b64 {%0,%1}, %2;" : "=f"(dlo), "=f"(dhi) : "l"(d2));
            m_lo[k] = fminf(m_lo[k], dlo);
            m_hi[k] = fminf(m_hi[k], dhi);
        }
    }
}

__global__ __launch_bounds__(THREADS, 1)
void cd_kernel(const float* __restrict__ vis,
               const float* __restrict__ tac,
               const float* __restrict__ model,
               const float* __restrict__ scale,
               const float* __restrict__ state,
               float* __restrict__ out,
               int nv, int nt, int nm,
               float wv, float wt, int nbp) {
    extern __shared__ float s_model[];          // nm pairs worst case
    __shared__ float s_par[13];
    __shared__ float s_min[NWARP * 128];
    __shared__ float s_m1[128];
    __shared__ int s_scan[NBIN];
    __shared__ int s_mstart[NBIN + 1];
    __shared__ int s_pstart[NBIN + 1];
    __shared__ int s_wlo_i, s_whi_i, s_slab0, s_np1, s_r0, s_r1, s_skip, s_last;

    const int tid  = threadIdx.x;
    const int lane = tid & 31;
    const int warp = tid >> 5;
    const int ntot0 = nv + nt;
    const int ntot = ntot0 < MAXP ? ntot0 : MAXP;
    const int nmm  = nm < MAXM ? nm : MAXM;
    const unsigned int GRID = gridDim.x;
    const int gstride = (int)GRID * THREADS;
    const int gtid = blockIdx.x * THREADS + tid;

    // ---- transform params ----
    if (tid == 0) {
        float oxs = state[3], oys = state[4], ozs = state[5];
        float sx = sinf(oxs), cx = cosf(oxs);
        float sy = sinf(oys), cy = cosf(oys);
        float sz = sinf(ozs), cz = cosf(ozs);
        s_par[0] = cz * cy;
        s_par[1] = cz * sy * sx - sz * cx;
        s_par[2] = cz * sy * cx + sz * sx;
        s_par[3] = sz * cy;
        s_par[4] = sz * sy * sx + cz * cx;
        s_par[5] = sz * sy * cx - cz * sx;
        s_par[6] = -sy;
        s_par[7] = cy * sx;
        s_par[8] = cy * cx;
        s_par[9]  = state[0];
        s_par[10] = state[1];
        s_par[11] = state[2];
        s_par[12] = 1.0f / scale[0];
    }
    __syncthreads();

    // ============ Phase A: histograms + pred transform ============
    for (int j = gtid; j < nmm; j += gstride) {
        float gx = model[3 * j], gy = model[3 * j + 1], gz = model[3 * j + 2];
        float b = fmaf(gx, gx, fmaf(gy, gy, gz * gz));
        atomicAdd(&g_mhist[norm_bin(sqrtf(b))], 1);
    }
    for (int i = gtid; i < ntot; i += gstride) {
        const float* src; int idx; float w;
        if (i < nv) { src = vis; idx = i;      w = wv; }
        else        { src = tac; idx = i - nv; w = wt; }
        float vx = src[3 * idx + 0] - s_par[9];
        float vy = src[3 * idx + 1] - s_par[10];
        float vz = src[3 * idx + 2] - s_par[11];
        float inv_s = s_par[12];
        float px = (vx * s_par[0] + vy * s_par[3] + vz * s_par[6]) * inv_s;
        float py = (vx * s_par[1] + vy * s_par[4] + vz * s_par[7]) * inv_s;
        float pz = (vx * s_par[2] + vy * s_par[5] + vz * s_par[8]) * inv_s;
        float a = fmaf(px, px, fmaf(py, py, pz * pz));
        float r = sqrtf(a);
        g_pu[i]  = make_float4(px, py, pz, a);
        g_pu2[i] = make_float2(w, r);
        atomicAdd(&g_phist[norm_bin(r)], 1);
    }
    grid_bar(&g_bar1, GRID);

    // ============ Phase B: every CTA scans the bin hists locally ============
    if (tid < NBIN) s_scan[tid] = g_mhist[tid];
    __syncthreads();
    for (int off = 1; off < NBIN; off <<= 1) {
        int t = (tid < NBIN && tid >= off) ? s_scan[tid - off] : 0;
        __syncthreads();
        if (tid < NBIN) s_scan[tid] += t;
        __syncthreads();
    }
    if (tid < NBIN) s_mstart[tid] = s_scan[tid] - g_mhist[tid];
    if (tid == 0) s_mstart[NBIN] = nmm;
    __syncthreads();
    if (tid < NBIN) s_scan[tid] = g_phist[tid];
    __syncthreads();
    for (int off = 1; off < NBIN; off <<= 1) {
        int t = (tid < NBIN && tid >= off) ? s_scan[tid - off] : 0;
        __syncthreads();
        if (tid < NBIN) s_scan[tid] += t;
        __syncthreads();
    }
    if (tid < NBIN) s_pstart[tid] = s_scan[tid] - g_phist[tid];
    if (tid == 0) s_pstart[NBIN] = ntot;
    __syncthreads();

    // ============ Phase C: scatter into norm order ============
    for (int j = gtid; j < nmm; j += gstride) {
        float gx = model[3 * j], gy = model[3 * j + 1], gz = model[3 * j + 2];
        float b = fmaf(gx, gx, fmaf(gy, gy, gz * gz));
        int bn = norm_bin(sqrtf(b));
        int pos = s_mstart[bn] + atomicAdd(&g_mcur[bn], 1);
        g_ms[pos] = make_float4(gx, gy, gz, b);
    }
    for (int i = gtid; i < ntot; i += gstride) {
        float4 P = g_pu[i]; float2 P2 = g_pu2[i];
        int bn = norm_bin(P2.y);
        int pos = s_pstart[bn] + atomicAdd(&g_pcur[bn], 1);
        g_ps[pos] = P; g_ps2[pos] = P2;
    }
    grid_bar(&g_bar2, GRID);

    // reset hist/cur for next replay (shadowed by Phase D)
    if (blockIdx.x == 0 && tid < NBIN) {
        g_mhist[tid] = 0; g_phist[tid] = 0; g_mcur[tid] = 0; g_pcur[tid] = 0;
    }

    // ============ Phase D: pruned chamfer per pred-block ============
    for (int pb = blockIdx.x; pb < nbp; pb += (int)GRID) {
        float a[4], wgt[4];
        uint64_t qx2[4], qy2[4], qz2[4];
        #pragma unroll
        for (int k = 0; k < 4; k++) {
            int i = pb * 128 + k * 32 + lane;
            float qx = 0.f, qy = 0.f, qz = 0.f;
            a[k] = 0.f; wgt[k] = 0.f;
            if (i < ntot) {
                float4 P = g_ps[i]; float2 P2 = g_ps2[i];
                qx = -2.0f * P.x; qy = -2.0f * P.y; qz = -2.0f * P.z;
                a[k] = P.w; wgt[k] = P2.x;
            }
            asm("mov.b64 %0, {%1,%1};" : "=l"(qx2[k]) : "f"(qx));
            asm("mov.b64 %0, {%1,%1};" : "=l"(qy2[k]) : "f"(qy));
            asm("mov.b64 %0, {%1,%1};" : "=l"(qz2[k]) : "f"(qz));
        }

        if (tid == 0) {
            s_wlo_i = 0x7f7fffff;
            s_whi_i = 0;
            int imid = pb * 128 + 64; if (imid >= ntot) imid = ntot - 1;
            float rmid = g_ps2[imid].y;
            int mrow = s_mstart[norm_bin(rmid)];
            int np1 = nmm < SLAB ? nmm : SLAB;
            int slab0 = mrow - np1 / 2;
            if (slab0 < 0) slab0 = 0;
            if (slab0 > nmm - np1) slab0 = nmm - np1;
            s_slab0 = slab0; s_np1 = np1;
        }
        __syncthreads();

        // ---- stage 1: slab scan for per-pred upper bound ----
        pack_rows(s_model, s_slab0, s_np1, tid);
        __syncthreads();
        {
            float m_lo[4], m_hi[4];
            #pragma unroll
            for (int k = 0; k < 4; k++) { m_lo[k] = FLT_MAX; m_hi[k] = FLT_MAX; }
            scan_pairs(s_model, (s_np1 + 1) >> 1, warp, qx2, qy2, qz2, m_lo, m_hi);
            #pragma unroll
            for (int k = 0; k < 4; k++)
                s_min[warp * 128 + k * 32 + lane] = fminf(m_lo[k], m_hi[k]);
        }
        __syncthreads();
        if (warp == 0) {
            #pragma unroll
            for (int k = 0; k < 4; k++) {
                int pidx = k * 32 + lane;
                float m = s_min[pidx];
                #pragma unroll
                for (int s = 1; s < NWARP; s++) m = fminf(m, s_min[s * 128 + pidx]);
                s_m1[pidx] = m;
                int i = pb * 128 + pidx;
                if (i < ntot) {
                    float r = g_ps2[i].y;
                    float W = sqrtf(fmaxf(a[k] + m, 0.f)) * 1.002f + 1e-5f;
                    float wlo = fmaxf(r - W, 0.f);
                    float whi = r + W;
                    atomicMin(&s_wlo_i, __float_as_int(wlo));
                    atomicMax(&s_whi_i, __float_as_int(whi));
                }
            }
        }
        __syncthreads();
        if (tid == 0) {
            float wlo = __int_as_float(s_wlo_i);
            float whi = __int_as_float(s_whi_i);
            int r0 = s_mstart[norm_bin(wlo)];
            int r1 = s_mstart[norm_bin(whi) + 1];
            s_r0 = r0; s_r1 = r1;
            s_skip = (r0 >= s_slab0 && r1 <= s_slab0 + s_np1) ? 1 : 0;
        }
        __syncthreads();

        // ---- stage 2: window scan, only if window escapes the slab ----
        if (!s_skip) {
            int r0 = s_r0, np2 = s_r1 - s_r0;
            pack_rows(s_model, r0, np2, tid);
            __syncthreads();
            float m_lo[4], m_hi[4];
            #pragma unroll
            for (int k = 0; k < 4; k++) {
                m_lo[k] = s_m1[k * 32 + lane];
                m_hi[k] = FLT_MAX;
            }
            scan_pairs(s_model, (np2 + 1) >> 1, warp, qx2, qy2, qz2, m_lo, m_hi);
            #pragma unroll
            for (int k = 0; k < 4; k++)
                s_min[warp * 128 + k * 32 + lane] = fminf(m_lo[k], m_hi[k]);
            __syncthreads();
            if (warp == 0) {
                #pragma unroll
                for (int k = 0; k < 4; k++) {
                    int pidx = k * 32 + lane;
                    float m = s_min[pidx];
                    #pragma unroll
                    for (int s = 1; s < NWARP; s++) m = fminf(m, s_min[s * 128 + pidx]);
                    s_m1[pidx] = m;
                }
            }
            __syncthreads();
        }

        // ---- block-weighted sum ----
        if (warp == 0) {
            float vsum = 0.0f;
            #pragma unroll
            for (int k = 0; k < 4; k++) {
                int pidx = k * 32 + lane;
                int i = pb * 128 + pidx;
                if (i < ntot) vsum += (a[k] + s_m1[pidx]) * wgt[k];
            }
            #pragma unroll
            for (int o = 16; o > 0; o >>= 1)
                vsum += __shfl_down_sync(0xffffffffu, vsum, o);
            if (lane == 0 && pb < NB_MAX) g_partials[pb] = vsum;
        }
        __syncthreads();
    }

    // ============ final fixed-order reduction ============
    if (tid == 0) {
        __threadfence();
        unsigned int t = atomicAdd(&g_ticket, 1u);
        s_last = (t == GRID - 1u) ? 1 : 0;
    }
    __syncthreads();
    if (s_last && warp == 0) {
        float s = 0.0f;
        for (int b = lane; b < nbp; b += 32)
            s += *((volatile float*)&g_partials[b]);
        #pragma unroll
        for (int o = 16; o > 0; o >>= 1)
            s += __shfl_down_sync(0xffffffffu, s, o);
        if (lane == 0) {
            out[0] = s;
            g_ticket = 0; g_bar1 = 0; g_bar2 = 0;   // reset for replay
        }
    }
}

extern "C" void kernel_launch(void* const* d_in, const int* in_sizes, int n_in,
                              void* d_out, int out_size) {
    const float* vis   = (const float*)d_in[0];  // visual_points  (16384,3)
    const float* tac   = (const float*)d_in[1];  // tactile_points (2048,3)
    const float* model = (const float*)d_in[2];  // model_points   (8192,3)
    const float* scale = (const float*)d_in[3];  // scalar
    const float* state = (const float*)d_in[4];  // (6,)
    float* out = (float*)d_out;

    int nv = in_sizes[0] / 3;
    int nt = in_sizes[1] / 3;
    int nm = in_sizes[2] / 3;

    int ntot = nv + nt;
    int nbp = (ntot + 127) / 128;               // 144 for default shapes
    if (nbp > NB_MAX) nbp = NB_MAX;
    int grid = nbp < 144 ? nbp : 144;           // all-resident for barriers

    int nmc = nm < MAXM ? nm : MAXM;
    int nm_pairs = (nmc + 1) / 2;
    size_t smem = (size_t)nm_pairs * 32;        // worst-case window = full model
    if (smem > 196608) smem = 196608;
    cudaFuncSetAttribute(cd_kernel, cudaFuncAttributeMaxDynamicSharedMemorySize,
                         (int)smem);

    float wv = 1.0f / (float)nv;
    float wt = 0.1f / (float)nt;

    cd_kernel<<<grid, THREADS, smem>>>(vis, tac, model, scale, state, out,
                                       nv, nt, nm, wv, wt, nbp);
}